// round 13
// baseline (speedup 1.0000x reference)
#include <cuda_runtime.h>

#define BN 1024   // B*N total nodes
#define NN 512    // nodes per batch
#define EB 8      // edges per barrier batch in agg

// ---------------- device scratch (no allocations allowed) ----------------
__device__ float g_X0[BN * 128];      // concat features after node MLP
__device__ float g_U[BN * 64];        // per-node u = x @ (W1a - W1b) + b1
__device__ float g_V[BN * 64];        // per-node v = x @ W1b
__device__ float g_ec[4][BN * 64];    // 0: ec1_out, 1: x2=ec2+ec1, 2: ec2_raw, 3: x3=ec3+ec2_raw
__device__ int   g_nbr[BN * NN];      // compacted neighbor indices (within-batch j)
__device__ int   g_cnt[BN];           // neighbor counts

// ---------------- K0: node MLP + concat -> g_X0 [BN,128] ----------------
__global__ void node_mlp_kernel(const float* __restrict__ coords,
                                const float* __restrict__ nf,
                                const float* __restrict__ cs,
                                const float* __restrict__ Wh1, const float* __restrict__ bh1,
                                const float* __restrict__ Wh2, const float* __restrict__ bh2) {
    int node = blockIdx.x;
    int t = threadIdx.x;  // 0..63
    __shared__ float x1s[64];
    float c0 = coords[node * 3 + 0];
    float c1 = coords[node * 3 + 1];
    float c2 = coords[node * 3 + 2];
    float a = bh1[t];
    a = fmaf(c0, Wh1[t], a);
    a = fmaf(c1, Wh1[64 + t], a);
    a = fmaf(c2, Wh1[128 + t], a);
    x1s[t] = fmaxf(a, 0.f);
    __syncthreads();
    // 2-way split accumulator to break the RAW chain
    float acc0 = bh2[t], acc1 = 0.f;
#pragma unroll
    for (int f = 0; f < 64; f += 2) {
        acc0 = fmaf(x1s[f], Wh2[f * 64 + t], acc0);
        acc1 = fmaf(x1s[f + 1], Wh2[(f + 1) * 64 + t], acc1);
    }
    g_X0[node * 128 + t] = fmaxf(acc0 + acc1, 0.f);
    g_X0[node * 128 + 64 + t] = (t < 63) ? nf[node * 63 + t] : cs[node];
}

// ---------------- K1: compact adjacency rows into neighbor lists ----------------
__global__ void build_nbrs_kernel(const float* __restrict__ A) {
    int node = blockIdx.x;            // 0..1023 ; A row offset = node*NN
    __shared__ int cnt_s;
    if (threadIdx.x == 0) cnt_s = 0;
    __syncthreads();
    int j = threadIdx.x;              // blockDim = 512
    if (A[(size_t)node * NN + j] > 0.f) {
        int s = atomicAdd(&cnt_s, 1);
        g_nbr[node * NN + s] = j;
    }
    __syncthreads();
    if (threadIdx.x == 0) g_cnt[node] = cnt_s;
}

// ---------------- K2a: per-node U/V for an EdgeConv layer ----------------
// u = x @ (W1[:F] - W1[F:]) + b1 ; v = x @ W1[F:]
// Then h1_ij = relu(u_i + v_j) reproduces relu([x_i, x_j - x_i] @ W1 + b1) exactly.
template <int F>
__global__ void uv_kernel(const float* __restrict__ W1, const float* __restrict__ b1,
                          int in_id) {
    int node = blockIdx.x;
    int t = threadIdx.x;  // 0..63
    const float* Xin = (F == 128) ? g_X0 : g_ec[in_id];
    __shared__ float xs[F];
#pragma unroll
    for (int f = t; f < F; f += 64) xs[f] = Xin[node * F + f];
    __syncthreads();
    // 4 independent chains (u0,u1,v0,v1)
    float u0 = b1[t], u1 = 0.f, v0 = 0.f, v1 = 0.f;
#pragma unroll
    for (int f = 0; f < F; f += 2) {
        float xa = xs[f], xb = xs[f + 1];
        float wa0 = W1[f * 64 + t];
        float wb0 = W1[(F + f) * 64 + t];
        float wa1 = W1[(f + 1) * 64 + t];
        float wb1 = W1[(F + f + 1) * 64 + t];
        u0 = fmaf(xa, wa0 - wb0, u0);
        v0 = fmaf(xa, wb0, v0);
        u1 = fmaf(xb, wa1 - wb1, u1);
        v1 = fmaf(xb, wb1, v1);
    }
    g_U[node * 64 + t] = u0 + u1;
    g_V[node * 64 + t] = v0 + v1;
}

// ---------------- K2b: sparse edge aggregation (layer-2 MLP + masked max) ----------
// out[node] = max_{j in nbrs} relu( relu(u_i + v_j) @ W2 + b2 )  (+ optional residual)
__global__ void agg_kernel(const float* __restrict__ W2, const float* __restrict__ b2,
                           int res_id, int out_id, int raw_id) {
    int node = blockIdx.x;
    int t = threadIdx.x;  // 0..63, thread t owns output channel t
    __shared__ float h1s[EB][64];
    __shared__ int js[NN];

    // W2 column t lives in registers: inner loop is pure LDS(broadcast)+FFMA
    float w2c[64];
#pragma unroll
    for (int f = 0; f < 64; f++) w2c[f] = W2[f * 64 + t];

    float u  = g_U[node * 64 + t];
    float bb = b2[t];
    int cnt  = g_cnt[node];
    int base = node & ~(NN - 1);  // batch base in node space

    for (int e = t; e < cnt; e += 64) js[e] = g_nbr[node * NN + e];
    __syncthreads();

    float m = -1e30f;
    // process edges in batches of EB: one barrier per batch, EB loads in flight
    for (int e0 = 0; e0 < cnt; e0 += EB) {
        int nb = min(EB, cnt - e0);
#pragma unroll
        for (int k = 0; k < EB; k++) {
            if (k < nb) {
                float vj = g_V[(base + js[e0 + k]) * 64 + t];
                h1s[k][t] = fmaxf(u + vj, 0.f);
            }
        }
        __syncthreads();
        for (int k = 0; k < nb; k++) {
            // 4 independent accumulator chains
            float a0 = bb, a1 = 0.f, a2 = 0.f, a3 = 0.f;
            const float4* h4 = reinterpret_cast<const float4*>(h1s[k]);
#pragma unroll
            for (int q = 0; q < 16; q++) {
                float4 h = h4[q];
                a0 = fmaf(h.x, w2c[4 * q + 0], a0);
                a1 = fmaf(h.y, w2c[4 * q + 1], a1);
                a2 = fmaf(h.z, w2c[4 * q + 2], a2);
                a3 = fmaf(h.w, w2c[4 * q + 3], a3);
            }
            float acc = (a0 + a1) + (a2 + a3);
            m = fmaxf(m, fmaxf(acc, 0.f));
        }
        __syncthreads();
    }

    float o = m;
    if (res_id >= 0) o += g_ec[res_id][node * 64 + t];
    g_ec[out_id][node * 64 + t] = o;
    if (raw_id >= 0) g_ec[raw_id][node * 64 + t] = m;
}

// ---------------- K3: head MLP -> output [BN,3] ----------------
__global__ void head_kernel(const float* __restrict__ Wh6, const float* __restrict__ bh6,
                            const float* __restrict__ Wout, const float* __restrict__ bout,
                            float* __restrict__ out) {
    int node = blockIdx.x;
    int t = threadIdx.x;  // 0..127
    __shared__ float xs[64];
    __shared__ float h6s[128];
    if (t < 64) xs[t] = g_ec[3][node * 64 + t];
    __syncthreads();
    float acc0 = bh6[t], acc1 = 0.f;
#pragma unroll
    for (int f = 0; f < 64; f += 2) {
        acc0 = fmaf(xs[f], Wh6[f * 128 + t], acc0);
        acc1 = fmaf(xs[f + 1], Wh6[(f + 1) * 128 + t], acc1);
    }
    h6s[t] = fmaxf(acc0 + acc1, 0.f);
    __syncthreads();
    if (t < 3) {
        float o0 = bout[t], o1 = 0.f, o2 = 0.f, o3 = 0.f;
#pragma unroll
        for (int f = 0; f < 128; f += 4) {
            o0 = fmaf(h6s[f], Wout[f * 3 + t], o0);
            o1 = fmaf(h6s[f + 1], Wout[(f + 1) * 3 + t], o1);
            o2 = fmaf(h6s[f + 2], Wout[(f + 2) * 3 + t], o2);
            o3 = fmaf(h6s[f + 3], Wout[(f + 3) * 3 + t], o3);
        }
        out[node * 3 + t] = fmaxf((o0 + o1) + (o2 + o3), 0.f);
    }
}

// ---------------- launch ----------------
extern "C" void kernel_launch(void* const* d_in, const int* in_sizes, int n_in,
                              void* d_out, int out_size) {
    const float* coords = (const float*)d_in[0];
    const float* A      = (const float*)d_in[1];
    const float* nf     = (const float*)d_in[2];
    const float* cs     = (const float*)d_in[3];
    const float* Wh1    = (const float*)d_in[4];
    const float* bh1    = (const float*)d_in[5];
    const float* Wh2    = (const float*)d_in[6];
    const float* bh2    = (const float*)d_in[7];
    const float* e1W1   = (const float*)d_in[8];
    const float* e1b1   = (const float*)d_in[9];
    const float* e1W2   = (const float*)d_in[10];
    const float* e1b2   = (const float*)d_in[11];
    const float* e2W1   = (const float*)d_in[12];
    const float* e2b1   = (const float*)d_in[13];
    const float* e2W2   = (const float*)d_in[14];
    const float* e2b2   = (const float*)d_in[15];
    const float* e3W1   = (const float*)d_in[16];
    const float* e3b1   = (const float*)d_in[17];
    const float* e3W2   = (const float*)d_in[18];
    const float* e3b2   = (const float*)d_in[19];
    const float* Wh6    = (const float*)d_in[20];
    const float* bh6    = (const float*)d_in[21];
    const float* Wout   = (const float*)d_in[22];
    const float* bout   = (const float*)d_in[23];
    float* out = (float*)d_out;

    node_mlp_kernel<<<BN, 64>>>(coords, nf, cs, Wh1, bh1, Wh2, bh2);
    build_nbrs_kernel<<<BN, NN>>>(A);

    // ec1: F=128 input, no residual; raw output -> g_ec[0]
    uv_kernel<128><<<BN, 64>>>(e1W1, e1b1, -1);
    agg_kernel<<<BN, 64>>>(e1W2, e1b2, /*res*/ -1, /*out*/ 0, /*raw*/ -1);

    // ec2: input ec1_out (g_ec[0]); out = raw + ec1_out -> g_ec[1]; raw -> g_ec[2]
    uv_kernel<64><<<BN, 64>>>(e2W1, e2b1, 0);
    agg_kernel<<<BN, 64>>>(e2W2, e2b2, /*res*/ 0, /*out*/ 1, /*raw*/ 2);

    // ec3: input x2 (g_ec[1]); out = raw + ec2_raw (g_ec[2]) -> g_ec[3]
    uv_kernel<64><<<BN, 64>>>(e3W1, e3b1, 1);
    agg_kernel<<<BN, 64>>>(e3W2, e3b2, /*res*/ 2, /*out*/ 3, /*raw*/ -1);

    head_kernel<<<BN, 128>>>(Wh6, bh6, Wout, bout, out);
}

// round 15
// speedup vs baseline: 1.2551x; 1.2551x over previous
#include <cuda_runtime.h>

#define BN 1024   // B*N total nodes
#define NN 512    // nodes per batch
#define EB 8      // edges per batch within a group

// ---------------- device scratch (no allocations allowed) ----------------
// U/V are DOUBLE-BUFFERED: fused kernels read buf p and write buf p^1 for the
// next layer. This removes the cross-block RAW race that broke R13 (agg reads
// neighbors' V globally; the uv tail must not overwrite it within the launch).
__device__ float g_U[2][BN * 64];
__device__ float g_V[2][BN * 64];
__device__ float g_ec0[BN * 64];      // ec1_out (residual for ec2)
__device__ float g_ec2raw[BN * 64];   // ec2 raw  (residual for ec3)
__device__ int   g_nbr[BN * NN];      // compacted neighbor indices (within-batch j)
__device__ int   g_cnt[BN];           // neighbor counts

// ---------------- packed fp32x2 helpers (sm_103a) ----------------
__device__ __forceinline__ void fma2(unsigned long long& acc,
                                     unsigned long long a, unsigned long long b) {
    asm("fma.rn.f32x2 %0, %1, %2, %3;" : "=l"(acc) : "l"(a), "l"(b), "l"(acc));
}
__device__ __forceinline__ unsigned long long pack2(float lo, float hi) {
    unsigned long long r;
    asm("mov.b64 %0, {%1, %2};" : "=l"(r) : "f"(lo), "f"(hi));
    return r;
}
__device__ __forceinline__ float2 unpack2(unsigned long long v) {
    float lo, hi;
    asm("mov.b64 {%0, %1}, %2;" : "=f"(lo), "=f"(hi) : "l"(v));
    return make_float2(lo, hi);
}

// ---------------- K0: adjacency compaction + node MLP + uv(layer1) -> buf 0 ----------
__global__ void k0_kernel(const float* __restrict__ coords, const float* __restrict__ A,
                          const float* __restrict__ nf, const float* __restrict__ cs,
                          const float* __restrict__ Wh1, const float* __restrict__ bh1,
                          const float* __restrict__ Wh2, const float* __restrict__ bh2,
                          const float* __restrict__ W1, const float* __restrict__ b1) {
    int node = blockIdx.x;
    int t = threadIdx.x;  // 0..511
    __shared__ int cnt_s;
    __shared__ float x1s[64];
    __shared__ float xs[128];
    if (t == 0) cnt_s = 0;
    __syncthreads();

    // adjacency row compaction (all 512 threads)
    if (A[(size_t)node * NN + t] > 0.f) {
        int s = atomicAdd(&cnt_s, 1);
        g_nbr[node * NN + s] = t;
    }
    // node MLP layer 1 (coords[3] -> 64)
    if (t < 64) {
        float c0 = coords[node * 3 + 0];
        float c1 = coords[node * 3 + 1];
        float c2 = coords[node * 3 + 2];
        float a = bh1[t];
        a = fmaf(c0, Wh1[t], a);
        a = fmaf(c1, Wh1[64 + t], a);
        a = fmaf(c2, Wh1[128 + t], a);
        x1s[t] = fmaxf(a, 0.f);
    }
    __syncthreads();
    if (t == 0) g_cnt[node] = cnt_s;
    // node MLP layer 2 + concat -> xs[128]
    if (t < 64) {
        float a0 = bh2[t], a1 = 0.f;
#pragma unroll
        for (int f = 0; f < 64; f += 2) {
            a0 = fmaf(x1s[f], Wh2[f * 64 + t], a0);
            a1 = fmaf(x1s[f + 1], Wh2[(f + 1) * 64 + t], a1);
        }
        xs[t] = fmaxf(a0 + a1, 0.f);
        xs[64 + t] = (t < 63) ? nf[node * 63 + t] : cs[node];
    }
    __syncthreads();
    // uv for EdgeConv1 (F=128): threads 0-63 -> u, 64-127 -> v (uniform per warp pair)
    if (t < 128) {
        int c = t & 63;
        bool isU = t < 64;
        float a0 = isU ? b1[c] : 0.f, a1 = 0.f;
#pragma unroll
        for (int f = 0; f < 128; f += 2) {
            float w0, w1;
            if (isU) {
                w0 = W1[f * 64 + c] - W1[(128 + f) * 64 + c];
                w1 = W1[(f + 1) * 64 + c] - W1[(128 + f + 1) * 64 + c];
            } else {
                w0 = W1[(128 + f) * 64 + c];
                w1 = W1[(128 + f + 1) * 64 + c];
            }
            a0 = fmaf(xs[f], w0, a0);
            a1 = fmaf(xs[f + 1], w1, a1);
        }
        if (isU) g_U[0][node * 64 + c] = a0 + a1;
        else     g_V[0][node * 64 + c] = a0 + a1;
    }
}

// ---------------- shared agg core: returns per-channel max m ----------------
// 128 threads = 2 groups x 64 channels; group g handles its half of the edge list.
// Reads U/V from buffer `rd` ONLY.
__device__ __forceinline__ float agg_core(int node, int t, int rd,
                                          const float* __restrict__ W2,
                                          const float* __restrict__ b2,
                                          int* js, float (*h1s)[EB][64], float (*gm)[64]) {
    int grp = t >> 6;
    int c = t & 63;

    // W2 column c as 32 packed f32x2 (pairs along input-feature f)
    unsigned long long w2p[32];
#pragma unroll
    for (int q = 0; q < 32; q++)
        w2p[q] = pack2(W2[(2 * q) * 64 + c], W2[(2 * q + 1) * 64 + c]);

    float u = g_U[rd][node * 64 + c];
    float bb = b2[c];
    int cnt = g_cnt[node];
    int base = node & ~(NN - 1);
    const float* Vr = g_V[rd];
    for (int e = t; e < cnt; e += 128) js[e] = g_nbr[node * NN + e];
    __syncthreads();

    int h = (cnt + 1) >> 1;
    int e0 = grp ? h : 0;
    int e1 = grp ? cnt : h;

    float m = -1e30f;
    for (int eb = e0; eb < e1; eb += EB) {
        int nb = min(EB, e1 - eb);
        float vv[EB];
#pragma unroll
        for (int k = 0; k < EB; k++)
            if (k < nb) vv[k] = Vr[(base + js[eb + k]) * 64 + c];
#pragma unroll
        for (int k = 0; k < EB; k++)
            if (k < nb) h1s[grp][k][c] = fmaxf(u + vv[k], 0.f);
        asm volatile("bar.sync %0, 64;" :: "r"(grp + 1) : "memory");
        for (int k = 0; k < nb; k++) {
            const ulonglong2* h8 = reinterpret_cast<const ulonglong2*>(h1s[grp][k]);
            unsigned long long a0 = 0, a1 = 0, a2 = 0, a3 = 0;
#pragma unroll
            for (int q = 0; q < 16; q += 2) {
                ulonglong2 p = h8[q];
                ulonglong2 p2 = h8[q + 1];
                fma2(a0, p.x, w2p[2 * q]);
                fma2(a1, p.y, w2p[2 * q + 1]);
                fma2(a2, p2.x, w2p[2 * q + 2]);
                fma2(a3, p2.y, w2p[2 * q + 3]);
            }
            float2 f0 = unpack2(a0), f1 = unpack2(a1), f2 = unpack2(a2), f3 = unpack2(a3);
            float acc = ((f0.x + f0.y) + (f1.x + f1.y)) +
                        ((f2.x + f2.y) + (f3.x + f3.y)) + bb;
            m = fmaxf(m, fmaxf(acc, 0.f));
        }
        asm volatile("bar.sync %0, 64;" :: "r"(grp + 1) : "memory");
    }
    gm[grp][c] = m;
    __syncthreads();
    return fmaxf(gm[0][c], gm[1][c]);
}

// ---------------- K_agg+uv: one EdgeConv aggregation + next layer's uv ----------------
// Reads U/V buf `rd`, writes next-layer U/V to buf `rd^1`.
__global__ void __launch_bounds__(128) agg_uv_kernel(
        const float* __restrict__ W2, const float* __restrict__ b2,
        int rd, int res_src, int store_out0, int store_raw2,
        const float* __restrict__ nW1, const float* __restrict__ nb1) {
    int node = blockIdx.x;
    int t = threadIdx.x;
    int c = t & 63;
    __shared__ int js[NN];
    __shared__ __align__(16) float h1s[2][EB][64];
    __shared__ float gm[2][64];
    __shared__ float xs[64];

    float mm = agg_core(node, t, rd, W2, b2, js, h1s, gm);

    if (t < 64) {
        float o = mm;
        if (res_src == 1) o += g_ec0[node * 64 + c];
        if (store_out0) g_ec0[node * 64 + c] = mm;      // ec1 raw==out (no residual on ec1)
        if (store_raw2) g_ec2raw[node * 64 + c] = mm;   // ec2 raw (pre-residual)
        xs[c] = o;
    }
    __syncthreads();
    // uv for next layer (F=64) -> write buffer rd^1
    {
        int wr = rd ^ 1;
        bool isU = t < 64;
        float a0 = isU ? nb1[c] : 0.f, a1 = 0.f;
#pragma unroll
        for (int f = 0; f < 64; f += 2) {
            float w0, w1;
            if (isU) {
                w0 = nW1[f * 64 + c] - nW1[(64 + f) * 64 + c];
                w1 = nW1[(f + 1) * 64 + c] - nW1[(64 + f + 1) * 64 + c];
            } else {
                w0 = nW1[(64 + f) * 64 + c];
                w1 = nW1[(64 + f + 1) * 64 + c];
            }
            a0 = fmaf(xs[f], w0, a0);
            a1 = fmaf(xs[f + 1], w1, a1);
        }
        if (isU) g_U[wr][node * 64 + c] = a0 + a1;
        else     g_V[wr][node * 64 + c] = a0 + a1;
    }
}

// ---------------- K3: EdgeConv3 aggregation + residual(ec2_raw) + head MLP ------------
__global__ void __launch_bounds__(128) agg_head_kernel(
        const float* __restrict__ W2, const float* __restrict__ b2, int rd,
        const float* __restrict__ Wh6, const float* __restrict__ bh6,
        const float* __restrict__ Wout, const float* __restrict__ bout,
        float* __restrict__ out) {
    int node = blockIdx.x;
    int t = threadIdx.x;
    int c = t & 63;
    __shared__ int js[NN];
    __shared__ __align__(16) float h1s[2][EB][64];
    __shared__ float gm[2][64];
    __shared__ float xs[64];
    __shared__ float h6s[128];

    float mm = agg_core(node, t, rd, W2, b2, js, h1s, gm);

    if (t < 64) xs[c] = mm + g_ec2raw[node * 64 + c];
    __syncthreads();
    // head layer 1: 64 -> 128, thread t owns channel t
    float a0 = bh6[t], a1 = 0.f;
#pragma unroll
    for (int f = 0; f < 64; f += 2) {
        a0 = fmaf(xs[f], Wh6[f * 128 + t], a0);
        a1 = fmaf(xs[f + 1], Wh6[(f + 1) * 128 + t], a1);
    }
    h6s[t] = fmaxf(a0 + a1, 0.f);
    __syncthreads();
    // head layer 2: 128 -> 3
    if (t < 3) {
        float o0 = bout[t], o1 = 0.f, o2 = 0.f, o3 = 0.f;
#pragma unroll
        for (int f = 0; f < 128; f += 4) {
            o0 = fmaf(h6s[f], Wout[f * 3 + t], o0);
            o1 = fmaf(h6s[f + 1], Wout[(f + 1) * 3 + t], o1);
            o2 = fmaf(h6s[f + 2], Wout[(f + 2) * 3 + t], o2);
            o3 = fmaf(h6s[f + 3], Wout[(f + 3) * 3 + t], o3);
        }
        out[node * 3 + t] = fmaxf((o0 + o1) + (o2 + o3), 0.f);
    }
}

// ---------------- launch ----------------
extern "C" void kernel_launch(void* const* d_in, const int* in_sizes, int n_in,
                              void* d_out, int out_size) {
    const float* coords = (const float*)d_in[0];
    const float* A      = (const float*)d_in[1];
    const float* nf     = (const float*)d_in[2];
    const float* cs     = (const float*)d_in[3];
    const float* Wh1    = (const float*)d_in[4];
    const float* bh1    = (const float*)d_in[5];
    const float* Wh2    = (const float*)d_in[6];
    const float* bh2    = (const float*)d_in[7];
    const float* e1W1   = (const float*)d_in[8];
    const float* e1b1   = (const float*)d_in[9];
    const float* e1W2   = (const float*)d_in[10];
    const float* e1b2   = (const float*)d_in[11];
    const float* e2W1   = (const float*)d_in[12];
    const float* e2b1   = (const float*)d_in[13];
    const float* e2W2   = (const float*)d_in[14];
    const float* e2b2   = (const float*)d_in[15];
    const float* e3W1   = (const float*)d_in[16];
    const float* e3b1   = (const float*)d_in[17];
    const float* e3W2   = (const float*)d_in[18];
    const float* e3b2   = (const float*)d_in[19];
    const float* Wh6    = (const float*)d_in[20];
    const float* bh6    = (const float*)d_in[21];
    const float* Wout   = (const float*)d_in[22];
    const float* bout   = (const float*)d_in[23];
    float* out = (float*)d_out;

    // K0: compaction + node MLP + uv(ec1) -> U/V buf 0
    k0_kernel<<<BN, NN>>>(coords, A, nf, cs, Wh1, bh1, Wh2, bh2, e1W1, e1b1);
    // ec1 agg (reads buf0; store ec1 out -> g_ec0) + uv(ec2) -> buf1
    agg_uv_kernel<<<BN, 128>>>(e1W2, e1b2, /*rd*/0, /*res*/0, /*out0*/1, /*raw2*/0, e2W1, e2b1);
    // ec2 agg (reads buf1; residual += ec1; store raw -> g_ec2raw) + uv(ec3) -> buf0
    agg_uv_kernel<<<BN, 128>>>(e2W2, e2b2, /*rd*/1, /*res*/1, /*out0*/0, /*raw2*/1, e3W1, e3b1);
    // ec3 agg (reads buf0; + ec2_raw residual) + head
    agg_head_kernel<<<BN, 128>>>(e3W2, e3b2, /*rd*/0, Wh6, bh6, Wout, bout, out);
}

// round 16
// speedup vs baseline: 1.3353x; 1.0639x over previous
#include <cuda_runtime.h>

#define BN 1024   // B*N total nodes
#define NN 512    // nodes per batch
#define EB 8      // edges per pipeline batch

typedef unsigned long long u64;

// ---------------- device scratch (no allocations allowed) ----------------
// U/V double-buffered: fused kernels read buf p, write buf p^1 (prevents the
// cross-block RAW race on neighbor V).
__device__ float g_U[2][BN * 64];
__device__ float g_V[2][BN * 64];
__device__ float g_ec0[BN * 64];      // ec1_out (residual for ec2)
__device__ float g_ec2raw[BN * 64];   // ec2 raw  (residual for ec3)
__device__ int   g_nbr[BN * NN];      // compacted neighbor indices
__device__ int   g_cnt[BN];           // neighbor counts
// packed layer-1 weights: Wd = W1a - W1b, Wv = W1b, pairs along f.
// layout: layer1 (64 q) at 0, layer2 (32 q) at 4096, layer3 (32 q) at 6144.
__device__ u64 g_Wdp[(64 + 32 + 32) * 64];
__device__ u64 g_Wvp[(64 + 32 + 32) * 64];

// ---------------- packed fp32x2 helpers (sm_103a) ----------------
__device__ __forceinline__ void fma2(u64& acc, u64 a, u64 b) {
    asm("fma.rn.f32x2 %0, %1, %2, %3;" : "=l"(acc) : "l"(a), "l"(b), "l"(acc));
}
__device__ __forceinline__ u64 pack2(float lo, float hi) {
    u64 r;
    asm("mov.b64 %0, {%1, %2};" : "=l"(r) : "f"(lo), "f"(hi));
    return r;
}
__device__ __forceinline__ float2 unpack2(u64 v) {
    float lo, hi;
    asm("mov.b64 {%0, %1}, %2;" : "=f"(lo), "=f"(hi) : "l"(v));
    return make_float2(lo, hi);
}

// ---------------- prep: pack Wd/Wv pairs for all three EdgeConv layers ------------
// grid = 128 blocks x 64 threads. blocks [0,64): layer1 (F=128); [64,96): layer2;
// [96,128): layer3 (F=64 each).
__global__ void prep_kernel(const float* __restrict__ W1a,
                            const float* __restrict__ W1b,
                            const float* __restrict__ W1c) {
    int b = blockIdx.x, c = threadIdx.x;
    const float* W; int F, q, off;
    if (b < 64)      { W = W1a; F = 128; q = b;      off = 0; }
    else if (b < 96) { W = W1b; F = 64;  q = b - 64; off = 4096; }
    else             { W = W1c; F = 64;  q = b - 96; off = 6144; }
    float a0 = W[(2 * q) * 64 + c];
    float a1 = W[(2 * q + 1) * 64 + c];
    float b0 = W[(F + 2 * q) * 64 + c];
    float b1 = W[(F + 2 * q + 1) * 64 + c];
    g_Wdp[off + q * 64 + c] = pack2(a0 - b0, a1 - b1);
    g_Wvp[off + q * 64 + c] = pack2(b0, b1);
}

// ---------------- K0: adjacency compaction + node MLP + uv(ec1) -> buf 0 ----------
__global__ void k0_kernel(const float* __restrict__ coords, const float* __restrict__ A,
                          const float* __restrict__ nf, const float* __restrict__ cs,
                          const float* __restrict__ Wh1, const float* __restrict__ bh1,
                          const float* __restrict__ Wh2, const float* __restrict__ bh2,
                          const float* __restrict__ b1) {
    int node = blockIdx.x;
    int t = threadIdx.x;  // 0..511
    __shared__ int cnt_s;
    __shared__ float x1s[64];
    __shared__ __align__(16) float xs[128];
    if (t == 0) cnt_s = 0;
    __syncthreads();

    if (A[(size_t)node * NN + t] > 0.f) {
        int s = atomicAdd(&cnt_s, 1);
        g_nbr[node * NN + s] = t;
    }
    if (t < 64) {
        float c0 = coords[node * 3 + 0];
        float c1 = coords[node * 3 + 1];
        float c2 = coords[node * 3 + 2];
        float a = bh1[t];
        a = fmaf(c0, Wh1[t], a);
        a = fmaf(c1, Wh1[64 + t], a);
        a = fmaf(c2, Wh1[128 + t], a);
        x1s[t] = fmaxf(a, 0.f);
    }
    __syncthreads();
    if (t == 0) g_cnt[node] = cnt_s;
    if (t < 64) {
        float a0 = bh2[t], a1 = 0.f;
#pragma unroll
        for (int f = 0; f < 64; f += 2) {
            a0 = fmaf(x1s[f], Wh2[f * 64 + t], a0);
            a1 = fmaf(x1s[f + 1], Wh2[(f + 1) * 64 + t], a1);
        }
        xs[t] = fmaxf(a0 + a1, 0.f);
        xs[64 + t] = (t < 63) ? nf[node * 63 + t] : cs[node];
    }
    __syncthreads();
    // uv for ec1 (F=128, 64 packed q): threads 0-63 -> u, 64-127 -> v
    if (t < 128) {
        int c = t & 63;
        bool isU = t < 64;
        const u64* Wp = (isU ? g_Wdp : g_Wvp);  // layer1 at offset 0
        const u64* xp = reinterpret_cast<const u64*>(xs);
        u64 a0 = 0, a1 = 0;
#pragma unroll
        for (int q = 0; q < 64; q += 2) {
            fma2(a0, xp[q], Wp[q * 64 + c]);
            fma2(a1, xp[q + 1], Wp[(q + 1) * 64 + c]);
        }
        float2 f0 = unpack2(a0), f1 = unpack2(a1);
        float r = (f0.x + f0.y) + (f1.x + f1.y) + (isU ? b1[c] : 0.f);
        if (isU) g_U[0][node * 64 + c] = r;
        else     g_V[0][node * 64 + c] = r;
    }
}

// ---------------- agg core: 64 threads (2 warps), one node ----------------
// Pipelined batches of EB edges: one __syncthreads per batch; next batch's V
// loads issued before the current dot; h1 double-buffered.
// Dot processes 2 edges concurrently (4 independent fma2 chains).
__device__ __forceinline__ float agg_core(int node, int c, int rd,
                                          const float* __restrict__ W2,
                                          const float* __restrict__ b2,
                                          int* js, float (*h1s)[EB][64]) {
    u64 w2p[32];
#pragma unroll
    for (int q = 0; q < 32; q++)
        w2p[q] = pack2(W2[(2 * q) * 64 + c], W2[(2 * q + 1) * 64 + c]);

    float u = g_U[rd][node * 64 + c];
    float bb = b2[c];
    int cnt = g_cnt[node];
    int base = node & ~(NN - 1);
    const float* Vr = g_V[rd];
    for (int e = c; e < cnt; e += 64) js[e] = g_nbr[node * NN + e];
    __syncthreads();

    // preload batch 0
    {
        int nb0 = min(EB, cnt);
        float vv[EB];
#pragma unroll
        for (int k = 0; k < EB; k++)
            if (k < nb0) vv[k] = Vr[(base + js[k]) * 64 + c];
#pragma unroll
        for (int k = 0; k < EB; k++)
            if (k < nb0) h1s[0][k][c] = fmaxf(u + vv[k], 0.f);
    }
    __syncthreads();

    float m = -1e30f;
    for (int eb = 0; eb < cnt; eb += EB) {
        int buf = (eb / EB) & 1;
        int nb = min(EB, cnt - eb);
        int nbn = min(EB, cnt - eb - EB);  // next batch size (<=0 if none)
        // issue next batch's V loads early (latency overlapped with dot)
        float vv[EB];
#pragma unroll
        for (int k = 0; k < EB; k++)
            if (k < nbn) vv[k] = Vr[(base + js[eb + EB + k]) * 64 + c];
        // dot over current batch, 2 edges in flight
        for (int k = 0; k < nb; k += 2) {
            bool two = (k + 1 < nb);
            const ulonglong2* hA = reinterpret_cast<const ulonglong2*>(h1s[buf][k]);
            const ulonglong2* hB = reinterpret_cast<const ulonglong2*>(h1s[buf][two ? k + 1 : k]);
            u64 a0 = 0, a1 = 0, b0 = 0, b1 = 0;
#pragma unroll
            for (int q = 0; q < 16; q++) {
                ulonglong2 pa = hA[q];
                ulonglong2 pb = hB[q];
                fma2(a0, pa.x, w2p[2 * q]);
                fma2(a1, pa.y, w2p[2 * q + 1]);
                fma2(b0, pb.x, w2p[2 * q]);
                fma2(b1, pb.y, w2p[2 * q + 1]);
            }
            float2 fa0 = unpack2(a0), fa1 = unpack2(a1);
            float accA = (fa0.x + fa0.y) + (fa1.x + fa1.y) + bb;
            m = fmaxf(m, fmaxf(accA, 0.f));
            if (two) {
                float2 fb0 = unpack2(b0), fb1 = unpack2(b1);
                float accB = (fb0.x + fb0.y) + (fb1.x + fb1.y) + bb;
                m = fmaxf(m, fmaxf(accB, 0.f));
            }
        }
        // produce next batch into the alternate buffer
#pragma unroll
        for (int k = 0; k < EB; k++)
            if (k < nbn) h1s[buf ^ 1][k][c] = fmaxf(u + vv[k], 0.f);
        __syncthreads();
    }
    return m;
}

// ---------------- agg + next-layer uv (reads buf rd, writes buf rd^1) --------------
__global__ void __launch_bounds__(64) agg_uv_kernel(
        const float* __restrict__ W2, const float* __restrict__ b2,
        int rd, int res_src, int store_out0, int store_raw2,
        int woff, const float* __restrict__ nb1) {
    int node = blockIdx.x;
    int c = threadIdx.x;  // 0..63
    __shared__ int js[NN];
    __shared__ __align__(16) float h1s[2][EB][64];
    __shared__ __align__(16) float xs[64];

    float mm = agg_core(node, c, rd, W2, b2, js, h1s);

    float o = mm;
    if (res_src == 1) o += g_ec0[node * 64 + c];
    if (store_out0) g_ec0[node * 64 + c] = mm;
    if (store_raw2) g_ec2raw[node * 64 + c] = mm;
    xs[c] = o;
    __syncthreads();
    // uv for next layer (F=64 -> 32 packed q), packed weights from prep
    {
        int wr = rd ^ 1;
        const u64* xp = reinterpret_cast<const u64*>(xs);
        const u64* Wd = g_Wdp + woff;
        const u64* Wv = g_Wvp + woff;
        u64 au = 0, av = 0;
#pragma unroll
        for (int q = 0; q < 32; q++) {
            u64 x = xp[q];
            fma2(au, x, Wd[q * 64 + c]);
            fma2(av, x, Wv[q * 64 + c]);
        }
        float2 fu = unpack2(au), fv = unpack2(av);
        g_U[wr][node * 64 + c] = fu.x + fu.y + nb1[c];
        g_V[wr][node * 64 + c] = fv.x + fv.y;
    }
}

// ---------------- ec3 agg + residual(ec2_raw) + head MLP -> out --------------------
__global__ void __launch_bounds__(64) agg_head_kernel(
        const float* __restrict__ W2, const float* __restrict__ b2, int rd,
        const float* __restrict__ Wh6, const float* __restrict__ bh6,
        const float* __restrict__ Wout, const float* __restrict__ bout,
        float* __restrict__ out) {
    int node = blockIdx.x;
    int c = threadIdx.x;  // 0..63
    __shared__ int js[NN];
    __shared__ __align__(16) float h1s[2][EB][64];
    __shared__ __align__(16) float xs[64];
    __shared__ float h6s[128];

    float mm = agg_core(node, c, rd, W2, b2, js, h1s);

    xs[c] = mm + g_ec2raw[node * 64 + c];
    __syncthreads();
    // head layer 1: 64 -> 128; thread c computes channels c and c+64
    {
        float a0 = bh6[c], a1 = 0.f, b0 = bh6[c + 64], b1 = 0.f;
#pragma unroll
        for (int f = 0; f < 64; f += 2) {
            float x0 = xs[f], x1 = xs[f + 1];
            a0 = fmaf(x0, Wh6[f * 128 + c], a0);
            b0 = fmaf(x0, Wh6[f * 128 + c + 64], b0);
            a1 = fmaf(x1, Wh6[(f + 1) * 128 + c], a1);
            b1 = fmaf(x1, Wh6[(f + 1) * 128 + c + 64], b1);
        }
        h6s[c] = fmaxf(a0 + a1, 0.f);
        h6s[c + 64] = fmaxf(b0 + b1, 0.f);
    }
    __syncthreads();
    // head layer 2: 128 -> 3
    if (c < 3) {
        float o0 = bout[c], o1 = 0.f, o2 = 0.f, o3 = 0.f;
#pragma unroll
        for (int f = 0; f < 128; f += 4) {
            o0 = fmaf(h6s[f], Wout[f * 3 + c], o0);
            o1 = fmaf(h6s[f + 1], Wout[(f + 1) * 3 + c], o1);
            o2 = fmaf(h6s[f + 2], Wout[(f + 2) * 3 + c], o2);
            o3 = fmaf(h6s[f + 3], Wout[(f + 3) * 3 + c], o3);
        }
        out[node * 3 + c] = fmaxf((o0 + o1) + (o2 + o3), 0.f);
    }
}

// ---------------- launch ----------------
extern "C" void kernel_launch(void* const* d_in, const int* in_sizes, int n_in,
                              void* d_out, int out_size) {
    const float* coords = (const float*)d_in[0];
    const float* A      = (const float*)d_in[1];
    const float* nf     = (const float*)d_in[2];
    const float* cs     = (const float*)d_in[3];
    const float* Wh1    = (const float*)d_in[4];
    const float* bh1    = (const float*)d_in[5];
    const float* Wh2    = (const float*)d_in[6];
    const float* bh2    = (const float*)d_in[7];
    const float* e1W1   = (const float*)d_in[8];
    const float* e1b1   = (const float*)d_in[9];
    const float* e1W2   = (const float*)d_in[10];
    const float* e1b2   = (const float*)d_in[11];
    const float* e2W1   = (const float*)d_in[12];
    const float* e2b1   = (const float*)d_in[13];
    const float* e2W2   = (const float*)d_in[14];
    const float* e2b2   = (const float*)d_in[15];
    const float* e3W1   = (const float*)d_in[16];
    const float* e3b1   = (const float*)d_in[17];
    const float* e3W2   = (const float*)d_in[18];
    const float* e3b2   = (const float*)d_in[19];
    const float* Wh6    = (const float*)d_in[20];
    const float* bh6    = (const float*)d_in[21];
    const float* Wout   = (const float*)d_in[22];
    const float* bout   = (const float*)d_in[23];
    float* out = (float*)d_out;

    // pack Wd/Wv for all three EdgeConv layer-1 weights
    prep_kernel<<<128, 64>>>(e1W1, e2W1, e3W1);
    // K0: compaction + node MLP + uv(ec1) -> buf 0
    k0_kernel<<<BN, NN>>>(coords, A, nf, cs, Wh1, bh1, Wh2, bh2, e1b1);
    // ec1 agg (buf0; store out -> g_ec0) + uv(ec2, packed off 4096) -> buf1
    agg_uv_kernel<<<BN, 64>>>(e1W2, e1b2, /*rd*/0, /*res*/0, /*out0*/1, /*raw2*/0,
                              /*woff*/4096, e2b1);
    // ec2 agg (buf1; += ec1; store raw -> g_ec2raw) + uv(ec3, off 6144) -> buf0
    agg_uv_kernel<<<BN, 64>>>(e2W2, e2b2, /*rd*/1, /*res*/1, /*out0*/0, /*raw2*/1,
                              /*woff*/6144, e3b1);
    // ec3 agg (buf0; + ec2_raw residual) + head
    agg_head_kernel<<<BN, 64>>>(e3W2, e3b2, /*rd*/0, Wh6, bh6, Wout, bout, out);
}

// round 17
// speedup vs baseline: 1.3410x; 1.0043x over previous
#include <cuda_runtime.h>

#define BN 1024   // B*N total nodes
#define NN 512    // nodes per batch
#define EB 8      // edges per pipeline batch

typedef unsigned long long u64;

// group barrier: 64 threads of group grp (ids 1 and 2)
#define GBAR(grp) asm volatile("bar.sync %0, 64;" :: "r"((grp) + 1) : "memory")

// ---------------- device scratch (no allocations allowed) ----------------
// U/V double-buffered: fused kernels read buf p, write buf p^1 (prevents the
// cross-block RAW race on neighbor V).
__device__ float g_U[2][BN * 64];
__device__ float g_V[2][BN * 64];
__device__ float g_ec0[BN * 64];      // ec1_out (residual for ec2)
__device__ float g_ec2raw[BN * 64];   // ec2 raw  (residual for ec3)
__device__ int   g_nbr[BN * NN];      // compacted neighbor indices
__device__ int   g_cnt[BN];           // neighbor counts
// packed layer-1 weights: Wd = W1a - W1b, Wv = W1b, pairs along f.
// layout: layer1 (64 q) at 0, layer2 (32 q) at 4096, layer3 (32 q) at 6144.
__device__ u64 g_Wdp[(64 + 32 + 32) * 64];
__device__ u64 g_Wvp[(64 + 32 + 32) * 64];

// ---------------- packed fp32x2 helpers (sm_103a) ----------------
__device__ __forceinline__ void fma2(u64& acc, u64 a, u64 b) {
    asm("fma.rn.f32x2 %0, %1, %2, %3;" : "=l"(acc) : "l"(a), "l"(b), "l"(acc));
}
__device__ __forceinline__ u64 pack2(float lo, float hi) {
    u64 r;
    asm("mov.b64 %0, {%1, %2};" : "=l"(r) : "f"(lo), "f"(hi));
    return r;
}
__device__ __forceinline__ float2 unpack2(u64 v) {
    float lo, hi;
    asm("mov.b64 {%0, %1}, %2;" : "=f"(lo), "=f"(hi) : "l"(v));
    return make_float2(lo, hi);
}

// ---------------- prep: pack Wd/Wv pairs for all three EdgeConv layers ------------
__global__ void prep_kernel(const float* __restrict__ W1a,
                            const float* __restrict__ W1b,
                            const float* __restrict__ W1c) {
    int b = blockIdx.x, c = threadIdx.x;
    const float* W; int F, q, off;
    if (b < 64)      { W = W1a; F = 128; q = b;      off = 0; }
    else if (b < 96) { W = W1b; F = 64;  q = b - 64; off = 4096; }
    else             { W = W1c; F = 64;  q = b - 96; off = 6144; }
    float a0 = W[(2 * q) * 64 + c];
    float a1 = W[(2 * q + 1) * 64 + c];
    float b0 = W[(F + 2 * q) * 64 + c];
    float b1 = W[(F + 2 * q + 1) * 64 + c];
    g_Wdp[off + q * 64 + c] = pack2(a0 - b0, a1 - b1);
    g_Wvp[off + q * 64 + c] = pack2(b0, b1);
}

// ---------------- K0: adjacency compaction + node MLP + uv(ec1) -> buf 0 ----------
__global__ void k0_kernel(const float* __restrict__ coords, const float* __restrict__ A,
                          const float* __restrict__ nf, const float* __restrict__ cs,
                          const float* __restrict__ Wh1, const float* __restrict__ bh1,
                          const float* __restrict__ Wh2, const float* __restrict__ bh2,
                          const float* __restrict__ b1) {
    int node = blockIdx.x;
    int t = threadIdx.x;  // 0..511
    __shared__ int cnt_s;
    __shared__ float x1s[64];
    __shared__ __align__(16) float xs[128];
    if (t == 0) cnt_s = 0;
    __syncthreads();

    if (A[(size_t)node * NN + t] > 0.f) {
        int s = atomicAdd(&cnt_s, 1);
        g_nbr[node * NN + s] = t;
    }
    if (t < 64) {
        float c0 = coords[node * 3 + 0];
        float c1 = coords[node * 3 + 1];
        float c2 = coords[node * 3 + 2];
        float a = bh1[t];
        a = fmaf(c0, Wh1[t], a);
        a = fmaf(c1, Wh1[64 + t], a);
        a = fmaf(c2, Wh1[128 + t], a);
        x1s[t] = fmaxf(a, 0.f);
    }
    __syncthreads();
    if (t == 0) g_cnt[node] = cnt_s;
    if (t < 64) {
        float a0 = bh2[t], a1 = 0.f;
#pragma unroll
        for (int f = 0; f < 64; f += 2) {
            a0 = fmaf(x1s[f], Wh2[f * 64 + t], a0);
            a1 = fmaf(x1s[f + 1], Wh2[(f + 1) * 64 + t], a1);
        }
        xs[t] = fmaxf(a0 + a1, 0.f);
        xs[64 + t] = (t < 63) ? nf[node * 63 + t] : cs[node];
    }
    __syncthreads();
    // uv for ec1 (F=128, 64 packed q): threads 0-63 -> u, 64-127 -> v
    if (t < 128) {
        int c = t & 63;
        bool isU = t < 64;
        const u64* Wp = (isU ? g_Wdp : g_Wvp);  // layer1 at offset 0
        const u64* xp = reinterpret_cast<const u64*>(xs);
        u64 a0 = 0, a1 = 0;
#pragma unroll
        for (int q = 0; q < 64; q += 2) {
            fma2(a0, xp[q], Wp[q * 64 + c]);
            fma2(a1, xp[q + 1], Wp[(q + 1) * 64 + c]);
        }
        float2 f0 = unpack2(a0), f1 = unpack2(a1);
        float r = (f0.x + f0.y) + (f1.x + f1.y) + (isU ? b1[c] : 0.f);
        if (isU) g_U[0][node * 64 + c] = r;
        else     g_V[0][node * 64 + c] = r;
    }
}

// ---------------- agg core: one node per 64-thread group --------------------
// Named barriers only (groups have divergent edge counts). Pipelined EB-edge
// batches; dot runs 2 edges concurrently (4 independent fma2 chains).
__device__ __forceinline__ float agg_core(int node, int c, int grp, int rd,
                                          const float* __restrict__ W2,
                                          const float* __restrict__ b2,
                                          int* js, float (*h1s)[EB][64]) {
    u64 w2p[32];
#pragma unroll
    for (int q = 0; q < 32; q++)
        w2p[q] = pack2(W2[(2 * q) * 64 + c], W2[(2 * q + 1) * 64 + c]);

    float u = g_U[rd][node * 64 + c];
    float bb = b2[c];
    int cnt = g_cnt[node];
    int base = node & ~(NN - 1);
    const float* Vr = g_V[rd];
    for (int e = c; e < cnt; e += 64) js[e] = g_nbr[node * NN + e];
    GBAR(grp);

    // preload batch 0
    {
        int nb0 = min(EB, cnt);
        float vv[EB];
#pragma unroll
        for (int k = 0; k < EB; k++)
            if (k < nb0) vv[k] = Vr[(base + js[k]) * 64 + c];
#pragma unroll
        for (int k = 0; k < EB; k++)
            if (k < nb0) h1s[0][k][c] = fmaxf(u + vv[k], 0.f);
    }
    GBAR(grp);

    float m = -1e30f;
    for (int eb = 0; eb < cnt; eb += EB) {
        int buf = (eb / EB) & 1;
        int nb = min(EB, cnt - eb);
        int nbn = min(EB, cnt - eb - EB);  // next batch size (<=0 if none)
        // issue next batch's V loads early (latency overlapped with dot)
        float vv[EB];
#pragma unroll
        for (int k = 0; k < EB; k++)
            if (k < nbn) vv[k] = Vr[(base + js[eb + EB + k]) * 64 + c];
        // dot over current batch, 2 edges in flight
        for (int k = 0; k < nb; k += 2) {
            bool two = (k + 1 < nb);
            const ulonglong2* hA = reinterpret_cast<const ulonglong2*>(h1s[buf][k]);
            const ulonglong2* hB = reinterpret_cast<const ulonglong2*>(h1s[buf][two ? k + 1 : k]);
            u64 a0 = 0, a1 = 0, b0 = 0, b1 = 0;
#pragma unroll
            for (int q = 0; q < 16; q++) {
                ulonglong2 pa = hA[q];
                ulonglong2 pb = hB[q];
                fma2(a0, pa.x, w2p[2 * q]);
                fma2(a1, pa.y, w2p[2 * q + 1]);
                fma2(b0, pb.x, w2p[2 * q]);
                fma2(b1, pb.y, w2p[2 * q + 1]);
            }
            float2 fa0 = unpack2(a0), fa1 = unpack2(a1);
            float accA = (fa0.x + fa0.y) + (fa1.x + fa1.y) + bb;
            m = fmaxf(m, fmaxf(accA, 0.f));
            if (two) {
                float2 fb0 = unpack2(b0), fb1 = unpack2(b1);
                float accB = (fb0.x + fb0.y) + (fb1.x + fb1.y) + bb;
                m = fmaxf(m, fmaxf(accB, 0.f));
            }
        }
        // produce next batch into the alternate buffer
#pragma unroll
        for (int k = 0; k < EB; k++)
            if (k < nbn) h1s[buf ^ 1][k][c] = fmaxf(u + vv[k], 0.f);
        GBAR(grp);
    }
    return m;
}

// ---------------- agg + next-layer uv: 2 nodes per 128-thread block ----------------
__global__ void __launch_bounds__(128) agg_uv_kernel(
        const float* __restrict__ W2, const float* __restrict__ b2,
        int rd, int res_src, int store_out0, int store_raw2,
        int woff, const float* __restrict__ nb1) {
    int t = threadIdx.x;
    int grp = t >> 6;                 // 0/1: independent node groups
    int c = t & 63;
    int node = blockIdx.x * 2 + grp;
    __shared__ int js[2][NN];
    __shared__ __align__(16) float h1s[2][2][EB][64];
    __shared__ __align__(16) float xs[2][64];

    float mm = agg_core(node, c, grp, rd, W2, b2, js[grp], h1s[grp]);

    float o = mm;
    if (res_src == 1) o += g_ec0[node * 64 + c];
    if (store_out0) g_ec0[node * 64 + c] = mm;
    if (store_raw2) g_ec2raw[node * 64 + c] = mm;
    xs[grp][c] = o;
    GBAR(grp);
    // uv for next layer (F=64 -> 32 packed q), packed weights from prep
    {
        int wr = rd ^ 1;
        const u64* xp = reinterpret_cast<const u64*>(xs[grp]);
        const u64* Wd = g_Wdp + woff;
        const u64* Wv = g_Wvp + woff;
        u64 au = 0, av = 0;
#pragma unroll
        for (int q = 0; q < 32; q++) {
            u64 x = xp[q];
            fma2(au, x, Wd[q * 64 + c]);
            fma2(av, x, Wv[q * 64 + c]);
        }
        float2 fu = unpack2(au), fv = unpack2(av);
        g_U[wr][node * 64 + c] = fu.x + fu.y + nb1[c];
        g_V[wr][node * 64 + c] = fv.x + fv.y;
    }
}

// ---------------- ec3 agg + residual(ec2_raw) + head MLP -> out --------------------
__global__ void __launch_bounds__(128) agg_head_kernel(
        const float* __restrict__ W2, const float* __restrict__ b2, int rd,
        const float* __restrict__ Wh6, const float* __restrict__ bh6,
        const float* __restrict__ Wout, const float* __restrict__ bout,
        float* __restrict__ out) {
    int t = threadIdx.x;
    int grp = t >> 6;
    int c = t & 63;
    int node = blockIdx.x * 2 + grp;
    __shared__ int js[2][NN];
    __shared__ __align__(16) float h1s[2][2][EB][64];
    __shared__ __align__(16) float xs[2][64];
    __shared__ float h6s[2][128];

    float mm = agg_core(node, c, grp, rd, W2, b2, js[grp], h1s[grp]);

    xs[grp][c] = mm + g_ec2raw[node * 64 + c];
    GBAR(grp);
    // head layer 1: 64 -> 128; thread c computes channels c and c+64 of its node
    {
        float a0 = bh6[c], a1 = 0.f, b0 = bh6[c + 64], b1 = 0.f;
        const float* x = xs[grp];
#pragma unroll
        for (int f = 0; f < 64; f += 2) {
            float x0 = x[f], x1 = x[f + 1];
            a0 = fmaf(x0, Wh6[f * 128 + c], a0);
            b0 = fmaf(x0, Wh6[f * 128 + c + 64], b0);
            a1 = fmaf(x1, Wh6[(f + 1) * 128 + c], a1);
            b1 = fmaf(x1, Wh6[(f + 1) * 128 + c + 64], b1);
        }
        h6s[grp][c] = fmaxf(a0 + a1, 0.f);
        h6s[grp][c + 64] = fmaxf(b0 + b1, 0.f);
    }
    GBAR(grp);
    // head layer 2: 128 -> 3
    if (c < 3) {
        const float* h6 = h6s[grp];
        float o0 = bout[c], o1 = 0.f, o2 = 0.f, o3 = 0.f;
#pragma unroll
        for (int f = 0; f < 128; f += 4) {
            o0 = fmaf(h6[f], Wout[f * 3 + c], o0);
            o1 = fmaf(h6[f + 1], Wout[(f + 1) * 3 + c], o1);
            o2 = fmaf(h6[f + 2], Wout[(f + 2) * 3 + c], o2);
            o3 = fmaf(h6[f + 3], Wout[(f + 3) * 3 + c], o3);
        }
        out[node * 3 + c] = fmaxf((o0 + o1) + (o2 + o3), 0.f);
    }
}

// ---------------- launch ----------------
extern "C" void kernel_launch(void* const* d_in, const int* in_sizes, int n_in,
                              void* d_out, int out_size) {
    const float* coords = (const float*)d_in[0];
    const float* A      = (const float*)d_in[1];
    const float* nf     = (const float*)d_in[2];
    const float* cs     = (const float*)d_in[3];
    const float* Wh1    = (const float*)d_in[4];
    const float* bh1    = (const float*)d_in[5];
    const float* Wh2    = (const float*)d_in[6];
    const float* bh2    = (const float*)d_in[7];
    const float* e1W1   = (const float*)d_in[8];
    const float* e1b1   = (const float*)d_in[9];
    const float* e1W2   = (const float*)d_in[10];
    const float* e1b2   = (const float*)d_in[11];
    const float* e2W1   = (const float*)d_in[12];
    const float* e2b1   = (const float*)d_in[13];
    const float* e2W2   = (const float*)d_in[14];
    const float* e2b2   = (const float*)d_in[15];
    const float* e3W1   = (const float*)d_in[16];
    const float* e3b1   = (const float*)d_in[17];
    const float* e3W2   = (const float*)d_in[18];
    const float* e3b2   = (const float*)d_in[19];
    const float* Wh6    = (const float*)d_in[20];
    const float* bh6    = (const float*)d_in[21];
    const float* Wout   = (const float*)d_in[22];
    const float* bout   = (const float*)d_in[23];
    float* out = (float*)d_out;

    // pack Wd/Wv for all three EdgeConv layer-1 weights
    prep_kernel<<<128, 64>>>(e1W1, e2W1, e3W1);
    // K0: compaction + node MLP + uv(ec1) -> buf 0
    k0_kernel<<<BN, NN>>>(coords, A, nf, cs, Wh1, bh1, Wh2, bh2, e1b1);
    // ec1 agg (buf0; store out -> g_ec0) + uv(ec2, packed off 4096) -> buf1
    agg_uv_kernel<<<BN / 2, 128>>>(e1W2, e1b2, /*rd*/0, /*res*/0, /*out0*/1, /*raw2*/0,
                                   /*woff*/4096, e2b1);
    // ec2 agg (buf1; += ec1; store raw -> g_ec2raw) + uv(ec3, off 6144) -> buf0
    agg_uv_kernel<<<BN / 2, 128>>>(e2W2, e2b2, /*rd*/1, /*res*/1, /*out0*/0, /*raw2*/1,
                                   /*woff*/6144, e3b1);
    // ec3 agg (buf0; + ec2_raw residual) + head
    agg_head_kernel<<<BN / 2, 128>>>(e3W2, e3b2, /*rd*/0, Wh6, bh6, Wout, bout, out);
}